// round 2
// baseline (speedup 1.0000x reference)
#include <cuda_runtime.h>
#include <cstdint>

#define N_TOK 16384
#define DIN   768
#define NEXP  8
#define HDIM  2048

#define BM 128
#define BN 128
#define BK 16
#define PA 20    // As pitch (floats)  -> conflict-free fragment loads
#define PB 136   // Bs pitch (floats)  -> conflict-free fragment loads

// ---------------- device scratch (no allocations allowed) ----------------
__device__ int   g_count[NEXP];
__device__ int   g_list[NEXP * N_TOK];
__device__ int   g_expert[N_TOK];
__device__ float g_prob[N_TOK];
__device__ float g_latent[(size_t)N_TOK * HDIM];   // 134 MB scratch

// ---------------- helpers ----------------
__device__ __forceinline__ uint32_t f2tf32(float v) {
    uint32_t r;
    asm("cvt.rna.tf32.f32 %0, %1;" : "=r"(r) : "f"(v));
    return r;
}

__device__ __forceinline__ void mma_tf32(float& c0, float& c1, float& c2, float& c3,
                                         uint32_t a0, uint32_t a1, uint32_t a2, uint32_t a3,
                                         uint32_t b0, uint32_t b1) {
    asm volatile("mma.sync.aligned.m16n8k8.row.col.f32.tf32.tf32.f32 "
                 "{%0,%1,%2,%3}, {%4,%5,%6,%7}, {%8,%9}, {%0,%1,%2,%3};\n"
                 : "+f"(c0), "+f"(c1), "+f"(c2), "+f"(c3)
                 : "r"(a0), "r"(a1), "r"(a2), "r"(a3), "r"(b0), "r"(b1));
}

// ---------------- small kernels ----------------
__global__ void zero_counts_kernel() {
    if (threadIdx.x < NEXP) g_count[threadIdx.x] = 0;
}

__global__ void router_kernel(const float* __restrict__ x,
                              const float* __restrict__ router_b,
                              const float* __restrict__ router) {
    const int warp = threadIdx.x >> 5, lane = threadIdx.x & 31;
    const int tok = blockIdx.x * 8 + warp;
    float acc[8];
#pragma unroll
    for (int e = 0; e < 8; e++) acc[e] = 0.f;
    const float* xr = x + (size_t)tok * DIN;
    for (int d = lane; d < DIN; d += 32) {
        float xv = xr[d] - router_b[d];
        float4 ra = *(const float4*)(router + d * 8);
        float4 rb = *(const float4*)(router + d * 8 + 4);
        acc[0] += xv * ra.x; acc[1] += xv * ra.y;
        acc[2] += xv * ra.z; acc[3] += xv * ra.w;
        acc[4] += xv * rb.x; acc[5] += xv * rb.y;
        acc[6] += xv * rb.z; acc[7] += xv * rb.w;
    }
#pragma unroll
    for (int e = 0; e < 8; e++) {
#pragma unroll
        for (int off = 16; off > 0; off >>= 1)
            acc[e] += __shfl_xor_sync(0xffffffffu, acc[e], off);
    }
    if (lane == 0) {
        float m = acc[0]; int idx = 0;
#pragma unroll
        for (int e = 1; e < 8; e++) if (acc[e] > m) { m = acc[e]; idx = e; }
        float s = 0.f;
#pragma unroll
        for (int e = 0; e < 8; e++) s += expf(acc[e] - m);
        g_expert[tok] = idx;
        g_prob[tok] = 1.f / s;   // max softmax prob
    }
}

__global__ void build_lists_kernel() {
    const int t = blockIdx.x * blockDim.x + threadIdx.x;
    if (t >= N_TOK) return;
    const int e = g_expert[t];
    const int pos = atomicAdd(&g_count[e], 1);
    g_list[e * N_TOK + pos] = t;
}

// ---------------- GEMM1: latent = relu(gather(x) @ enc[e]) ----------------
__global__ __launch_bounds__(256)
void gemm1_kernel(const float* __restrict__ x, const float* __restrict__ enc) {
    const int e = blockIdx.z;
    const int cnt = g_count[e];
    const int mBase = blockIdx.y * BM;
    if (mBase >= cnt) return;
    const int nBase = blockIdx.x * BN;

    __shared__ uint32_t As[2][BM * PA];
    __shared__ uint32_t Bs[2][BK * PB];

    const int tid = threadIdx.x;
    const int lane = tid & 31, warp = tid >> 5;
    const int wm = (warp >> 2) * 64, wn = (warp & 3) * 32;
    const int grp = lane >> 2, tig = lane & 3;

    const int* list = g_list + e * N_TOK;
    const float* B = enc + (size_t)e * DIN * HDIM;

    const int arow0 = tid >> 2;          // 0..63
    const int arow1 = arow0 + 64;        // 64..127
    const int aq = tid & 3;
    const int tok0 = (mBase + arow0 < cnt) ? list[mBase + arow0] : -1;
    const int tok1 = (mBase + arow1 < cnt) ? list[mBase + arow1] : -1;

    const int brow0 = tid >> 5;          // 0..7
    const int brow1 = brow0 + 8;
    const int bq = tid & 31;

    float4 av0, av1, bv0, bv1;

    auto fetch = [&](int kt) {
        const int k0 = kt * BK;
        av0 = (tok0 >= 0) ? *(const float4*)(x + (size_t)tok0 * DIN + k0 + aq * 4)
                          : make_float4(0.f, 0.f, 0.f, 0.f);
        av1 = (tok1 >= 0) ? *(const float4*)(x + (size_t)tok1 * DIN + k0 + aq * 4)
                          : make_float4(0.f, 0.f, 0.f, 0.f);
        bv0 = *(const float4*)(B + (size_t)(k0 + brow0) * HDIM + nBase + bq * 4);
        bv1 = *(const float4*)(B + (size_t)(k0 + brow1) * HDIM + nBase + bq * 4);
    };
    auto stage = [&](int buf) {
        uint32_t* a = As[buf];
        a[arow0 * PA + aq * 4 + 0] = f2tf32(av0.x);
        a[arow0 * PA + aq * 4 + 1] = f2tf32(av0.y);
        a[arow0 * PA + aq * 4 + 2] = f2tf32(av0.z);
        a[arow0 * PA + aq * 4 + 3] = f2tf32(av0.w);
        a[arow1 * PA + aq * 4 + 0] = f2tf32(av1.x);
        a[arow1 * PA + aq * 4 + 1] = f2tf32(av1.y);
        a[arow1 * PA + aq * 4 + 2] = f2tf32(av1.z);
        a[arow1 * PA + aq * 4 + 3] = f2tf32(av1.w);
        uint32_t* b = Bs[buf];
        b[brow0 * PB + bq * 4 + 0] = f2tf32(bv0.x);
        b[brow0 * PB + bq * 4 + 1] = f2tf32(bv0.y);
        b[brow0 * PB + bq * 4 + 2] = f2tf32(bv0.z);
        b[brow0 * PB + bq * 4 + 3] = f2tf32(bv0.w);
        b[brow1 * PB + bq * 4 + 0] = f2tf32(bv1.x);
        b[brow1 * PB + bq * 4 + 1] = f2tf32(bv1.y);
        b[brow1 * PB + bq * 4 + 2] = f2tf32(bv1.z);
        b[brow1 * PB + bq * 4 + 3] = f2tf32(bv1.w);
    };

    float c[4][4][4];
#pragma unroll
    for (int mi = 0; mi < 4; mi++)
#pragma unroll
        for (int ni = 0; ni < 4; ni++)
#pragma unroll
            for (int j = 0; j < 4; j++) c[mi][ni][j] = 0.f;

    fetch(0); stage(0);
    __syncthreads();

    const int KT = DIN / BK;   // 48
    for (int kt = 0; kt < KT; ++kt) {
        const int buf = kt & 1;
        if (kt + 1 < KT) fetch(kt + 1);
#pragma unroll
        for (int ks = 0; ks < BK; ks += 8) {
            uint32_t aF[4][4], bF[4][2];
#pragma unroll
            for (int mi = 0; mi < 4; mi++) {
                const int m = wm + mi * 16;
                aF[mi][0] = As[buf][(m + grp) * PA + ks + tig];
                aF[mi][1] = As[buf][(m + grp + 8) * PA + ks + tig];
                aF[mi][2] = As[buf][(m + grp) * PA + ks + tig + 4];
                aF[mi][3] = As[buf][(m + grp + 8) * PA + ks + tig + 4];
            }
#pragma unroll
            for (int ni = 0; ni < 4; ni++) {
                const int n = wn + ni * 8;
                bF[ni][0] = Bs[buf][(ks + tig) * PB + n + grp];
                bF[ni][1] = Bs[buf][(ks + tig + 4) * PB + n + grp];
            }
#pragma unroll
            for (int mi = 0; mi < 4; mi++)
#pragma unroll
                for (int ni = 0; ni < 4; ni++)
                    mma_tf32(c[mi][ni][0], c[mi][ni][1], c[mi][ni][2], c[mi][ni][3],
                             aF[mi][0], aF[mi][1], aF[mi][2], aF[mi][3],
                             bF[ni][0], bF[ni][1]);
        }
        if (kt + 1 < KT) stage(buf ^ 1);
        __syncthreads();
    }

    // epilogue: relu -> latent scratch (indexed by original token id)
#pragma unroll
    for (int mi = 0; mi < 4; mi++) {
        const int r0 = mBase + wm + mi * 16 + grp;
        const int r1 = r0 + 8;
        const int t0 = (r0 < cnt) ? list[r0] : -1;
        const int t1 = (r1 < cnt) ? list[r1] : -1;
#pragma unroll
        for (int ni = 0; ni < 4; ni++) {
            const int col = nBase + wn + ni * 8 + tig * 2;
            if (t0 >= 0) {
                float2 v = make_float2(fmaxf(c[mi][ni][0], 0.f), fmaxf(c[mi][ni][1], 0.f));
                *(float2*)(g_latent + (size_t)t0 * HDIM + col) = v;
            }
            if (t1 >= 0) {
                float2 v = make_float2(fmaxf(c[mi][ni][2], 0.f), fmaxf(c[mi][ni][3], 0.f));
                *(float2*)(g_latent + (size_t)t1 * HDIM + col) = v;
            }
        }
    }
}

// ---------------- GEMM2: out = prob * (gather(latent) @ dec[e]) + pre_b ----------------
__global__ __launch_bounds__(256)
void gemm2_kernel(const float* __restrict__ dec, const float* __restrict__ pre_b,
                  float* __restrict__ out) {
    const int e = blockIdx.z;
    const int cnt = g_count[e];
    const int mBase = blockIdx.y * BM;
    if (mBase >= cnt) return;
    const int nBase = blockIdx.x * BN;

    __shared__ uint32_t As[2][BM * PA];
    __shared__ uint32_t Bs[2][BK * PB];

    const int tid = threadIdx.x;
    const int lane = tid & 31, warp = tid >> 5;
    const int wm = (warp >> 2) * 64, wn = (warp & 3) * 32;
    const int grp = lane >> 2, tig = lane & 3;

    const int* list = g_list + e * N_TOK;
    const float* B = dec + (size_t)e * HDIM * DIN;

    const int arow0 = tid >> 2;
    const int arow1 = arow0 + 64;
    const int aq = tid & 3;
    const int tok0 = (mBase + arow0 < cnt) ? list[mBase + arow0] : -1;
    const int tok1 = (mBase + arow1 < cnt) ? list[mBase + arow1] : -1;

    const int brow0 = tid >> 5;
    const int brow1 = brow0 + 8;
    const int bq = tid & 31;

    float4 av0, av1, bv0, bv1;

    auto fetch = [&](int kt) {
        const int k0 = kt * BK;
        av0 = (tok0 >= 0) ? *(const float4*)(g_latent + (size_t)tok0 * HDIM + k0 + aq * 4)
                          : make_float4(0.f, 0.f, 0.f, 0.f);
        av1 = (tok1 >= 0) ? *(const float4*)(g_latent + (size_t)tok1 * HDIM + k0 + aq * 4)
                          : make_float4(0.f, 0.f, 0.f, 0.f);
        bv0 = *(const float4*)(B + (size_t)(k0 + brow0) * DIN + nBase + bq * 4);
        bv1 = *(const float4*)(B + (size_t)(k0 + brow1) * DIN + nBase + bq * 4);
    };
    auto stage = [&](int buf) {
        uint32_t* a = As[buf];
        a[arow0 * PA + aq * 4 + 0] = f2tf32(av0.x);
        a[arow0 * PA + aq * 4 + 1] = f2tf32(av0.y);
        a[arow0 * PA + aq * 4 + 2] = f2tf32(av0.z);
        a[arow0 * PA + aq * 4 + 3] = f2tf32(av0.w);
        a[arow1 * PA + aq * 4 + 0] = f2tf32(av1.x);
        a[arow1 * PA + aq * 4 + 1] = f2tf32(av1.y);
        a[arow1 * PA + aq * 4 + 2] = f2tf32(av1.z);
        a[arow1 * PA + aq * 4 + 3] = f2tf32(av1.w);
        uint32_t* b = Bs[buf];
        b[brow0 * PB + bq * 4 + 0] = f2tf32(bv0.x);
        b[brow0 * PB + bq * 4 + 1] = f2tf32(bv0.y);
        b[brow0 * PB + bq * 4 + 2] = f2tf32(bv0.z);
        b[brow0 * PB + bq * 4 + 3] = f2tf32(bv0.w);
        b[brow1 * PB + bq * 4 + 0] = f2tf32(bv1.x);
        b[brow1 * PB + bq * 4 + 1] = f2tf32(bv1.y);
        b[brow1 * PB + bq * 4 + 2] = f2tf32(bv1.z);
        b[brow1 * PB + bq * 4 + 3] = f2tf32(bv1.w);
    };

    float c[4][4][4];
#pragma unroll
    for (int mi = 0; mi < 4; mi++)
#pragma unroll
        for (int ni = 0; ni < 4; ni++)
#pragma unroll
            for (int j = 0; j < 4; j++) c[mi][ni][j] = 0.f;

    fetch(0); stage(0);
    __syncthreads();

    const int KT = HDIM / BK;  // 128
    for (int kt = 0; kt < KT; ++kt) {
        const int buf = kt & 1;
        if (kt + 1 < KT) fetch(kt + 1);
#pragma unroll
        for (int ks = 0; ks < BK; ks += 8) {
            uint32_t aF[4][4], bF[4][2];
#pragma unroll
            for (int mi = 0; mi < 4; mi++) {
                const int m = wm + mi * 16;
                aF[mi][0] = As[buf][(m + grp) * PA + ks + tig];
                aF[mi][1] = As[buf][(m + grp + 8) * PA + ks + tig];
                aF[mi][2] = As[buf][(m + grp) * PA + ks + tig + 4];
                aF[mi][3] = As[buf][(m + grp + 8) * PA + ks + tig + 4];
            }
#pragma unroll
            for (int ni = 0; ni < 4; ni++) {
                const int n = wn + ni * 8;
                bF[ni][0] = Bs[buf][(ks + tig) * PB + n + grp];
                bF[ni][1] = Bs[buf][(ks + tig + 4) * PB + n + grp];
            }
#pragma unroll
            for (int mi = 0; mi < 4; mi++)
#pragma unroll
                for (int ni = 0; ni < 4; ni++)
                    mma_tf32(c[mi][ni][0], c[mi][ni][1], c[mi][ni][2], c[mi][ni][3],
                             aF[mi][0], aF[mi][1], aF[mi][2], aF[mi][3],
                             bF[ni][0], bF[ni][1]);
        }
        if (kt + 1 < KT) stage(buf ^ 1);
        __syncthreads();
    }

    // epilogue: scale by max-prob, add pre_b, scatter to original token rows
#pragma unroll
    for (int mi = 0; mi < 4; mi++) {
        const int r0 = mBase + wm + mi * 16 + grp;
        const int r1 = r0 + 8;
        const int t0 = (r0 < cnt) ? list[r0] : -1;
        const int t1 = (r1 < cnt) ? list[r1] : -1;
        const float p0 = (t0 >= 0) ? g_prob[t0] : 0.f;
        const float p1 = (t1 >= 0) ? g_prob[t1] : 0.f;
#pragma unroll
        for (int ni = 0; ni < 4; ni++) {
            const int col = nBase + wn + ni * 8 + tig * 2;
            const float pb0 = pre_b[col], pb1 = pre_b[col + 1];
            if (t0 >= 0) {
                float2 v = make_float2(p0 * c[mi][ni][0] + pb0, p0 * c[mi][ni][1] + pb1);
                *(float2*)(out + (size_t)t0 * DIN + col) = v;
            }
            if (t1 >= 0) {
                float2 v = make_float2(p1 * c[mi][ni][2] + pb0, p1 * c[mi][ni][3] + pb1);
                *(float2*)(out + (size_t)t1 * DIN + col) = v;
            }
        }
    }
}

// ---------------- launcher ----------------
extern "C" void kernel_launch(void* const* d_in, const int* in_sizes, int n_in,
                              void* d_out, int out_size) {
    const float* x        = (const float*)d_in[0];
    const float* pre_b    = (const float*)d_in[1];
    const float* enc      = (const float*)d_in[2];
    const float* dec      = (const float*)d_in[3];
    const float* router_b = (const float*)d_in[4];
    const float* router   = (const float*)d_in[5];
    float* out = (float*)d_out;

    zero_counts_kernel<<<1, 32>>>();
    router_kernel<<<N_TOK / 8, 256>>>(x, router_b, router);
    build_lists_kernel<<<N_TOK / 256, 256>>>();

    dim3 g1(HDIM / BN, N_TOK / BM, NEXP);   // (16, 128, 8) — most tiles early-exit
    gemm1_kernel<<<g1, 256>>>(x, enc);

    dim3 g2(DIN / BN, N_TOK / BM, NEXP);    // (6, 128, 8)
    gemm2_kernel<<<g2, 256>>>(dec, pre_b, out);
}

// round 4
// speedup vs baseline: 1.2881x; 1.2881x over previous
#include <cuda_runtime.h>
#include <cuda_fp16.h>
#include <cstdint>

#define N_TOK 16384
#define DIN   768
#define NEXP  8
#define HDIM  2048

#define PITCH 40   // smem row pitch in halfs (80B = 5*16B -> conflict-free fragments)

// ---------------- device scratch ----------------
__device__ int    g_count[NEXP];
__device__ int    g_list[NEXP * N_TOK];
__device__ int    g_expert[N_TOK];
__device__ float  g_prob[N_TOK];
__device__ __half g_latent[(size_t)N_TOK * HDIM];   // 67 MB fp16 scratch

// ---------------- mma helper ----------------
__device__ __forceinline__ void mma_f16(float& c0, float& c1, float& c2, float& c3,
                                        uint32_t a0, uint32_t a1, uint32_t a2, uint32_t a3,
                                        uint32_t b0, uint32_t b1) {
    asm volatile("mma.sync.aligned.m16n8k16.row.col.f32.f16.f16.f32 "
                 "{%0,%1,%2,%3}, {%4,%5,%6,%7}, {%8,%9}, {%0,%1,%2,%3};\n"
                 : "+f"(c0), "+f"(c1), "+f"(c2), "+f"(c3)
                 : "r"(a0), "r"(a1), "r"(a2), "r"(a3), "r"(b0), "r"(b1));
}

// ---------------- small kernels ----------------
__global__ void zero_counts_kernel() {
    if (threadIdx.x < NEXP) g_count[threadIdx.x] = 0;
}

__global__ void router_kernel(const float* __restrict__ x,
                              const float* __restrict__ router_b,
                              const float* __restrict__ router) {
    const int warp = threadIdx.x >> 5, lane = threadIdx.x & 31;
    const int tok = blockIdx.x * 8 + warp;
    float acc[8];
#pragma unroll
    for (int e = 0; e < 8; e++) acc[e] = 0.f;
    const float* xr = x + (size_t)tok * DIN;
    for (int d = lane; d < DIN; d += 32) {
        float xv = xr[d] - router_b[d];
        float4 ra = *(const float4*)(router + d * 8);
        float4 rb = *(const float4*)(router + d * 8 + 4);
        acc[0] += xv * ra.x; acc[1] += xv * ra.y;
        acc[2] += xv * ra.z; acc[3] += xv * ra.w;
        acc[4] += xv * rb.x; acc[5] += xv * rb.y;
        acc[6] += xv * rb.z; acc[7] += xv * rb.w;
    }
#pragma unroll
    for (int e = 0; e < 8; e++) {
#pragma unroll
        for (int off = 16; off > 0; off >>= 1)
            acc[e] += __shfl_xor_sync(0xffffffffu, acc[e], off);
    }
    if (lane == 0) {
        float m = acc[0]; int idx = 0;
#pragma unroll
        for (int e = 1; e < 8; e++) if (acc[e] > m) { m = acc[e]; idx = e; }
        float s = 0.f;
#pragma unroll
        for (int e = 0; e < 8; e++) s += expf(acc[e] - m);
        g_expert[tok] = idx;
        g_prob[tok] = 1.f / s;
    }
}

__global__ void build_lists_kernel() {
    const int t = blockIdx.x * blockDim.x + threadIdx.x;
    if (t >= N_TOK) return;
    const int e = g_expert[t];
    const int pos = atomicAdd(&g_count[e], 1);
    g_list[e * N_TOK + pos] = t;
}

// ---------------- fp16 tensor-core gather-GEMM ----------------
// Tile 128x128, BK=32 halfs. A gathered token rows (fp32->fp16 or fp16 direct),
// B transposed-staged [n][k]. 8 warps, 64x32 warp tiles, m16n8k16 mma.
template<int KTOT, bool G1>
__global__ void __launch_bounds__(256, 2) sae_gemm_kernel(
    const float* __restrict__ Ax, const float* __restrict__ W,
    const float* __restrict__ pre_b, float* __restrict__ out)
{
    const int e = blockIdx.z;
    const int cnt = g_count[e];
    const int mBase = blockIdx.y * 128;
    if (mBase >= cnt) return;
    const int nBase = blockIdx.x * 128;
    const int ldB = G1 ? HDIM : DIN;
    const float* We = W + (size_t)e * KTOT * ldB;
    const int* list = g_list + e * N_TOK;

    __shared__ __half As[2][128 * PITCH];
    __shared__ __half Bs[2][128 * PITCH];

    const int tid = threadIdx.x, lane = tid & 31, warp = tid >> 5;
    const int wm = (warp >> 2) * 64, wn = (warp & 3) * 32;
    const int grp = lane >> 2, tig = lane & 3;

    // staging ids: 2 threads per row, each 16 halfs of the 32-half K-chunk
    const int sRow = tid >> 1, sHalf = tid & 1;
    const int tokA = (mBase + sRow < cnt) ? list[mBase + sRow] : -1;

    float4 av[4];      // G1 A fetch (16 f32)
    uint4  al[2];      // G2 A fetch (16 fp16)
    float  bf[16];     // B fetch (strided f32)

    auto fetch = [&](int c) {
        const int k0 = c * 32 + sHalf * 16;
        if (G1) {
            if (tokA >= 0) {
                const float4* p = (const float4*)(Ax + (size_t)tokA * KTOT + k0);
                av[0] = __ldg(p); av[1] = __ldg(p + 1); av[2] = __ldg(p + 2); av[3] = __ldg(p + 3);
            } else {
                av[0] = av[1] = av[2] = av[3] = make_float4(0.f, 0.f, 0.f, 0.f);
            }
        } else {
            if (tokA >= 0) {
                const uint4* p = (const uint4*)(g_latent + (size_t)tokA * KTOT + k0);
                al[0] = __ldg(p); al[1] = __ldg(p + 1);
            } else {
                al[0] = al[1] = make_uint4(0u, 0u, 0u, 0u);
            }
        }
        const float* bp = We + (size_t)k0 * ldB + nBase + sRow;   // sRow = n index
#pragma unroll
        for (int j = 0; j < 16; j++) bf[j] = __ldg(bp + (size_t)j * ldB);
    };

    auto stage = [&](int buf) {
        __half* a = &As[buf][sRow * PITCH + sHalf * 16];
        if (G1) {
            __half2 h[8];
            h[0] = __floats2half2_rn(av[0].x, av[0].y); h[1] = __floats2half2_rn(av[0].z, av[0].w);
            h[2] = __floats2half2_rn(av[1].x, av[1].y); h[3] = __floats2half2_rn(av[1].z, av[1].w);
            h[4] = __floats2half2_rn(av[2].x, av[2].y); h[5] = __floats2half2_rn(av[2].z, av[2].w);
            h[6] = __floats2half2_rn(av[3].x, av[3].y); h[7] = __floats2half2_rn(av[3].z, av[3].w);
            uint4* q = reinterpret_cast<uint4*>(h);
            ((uint4*)a)[0] = q[0];
            ((uint4*)a)[1] = q[1];
        } else {
            ((uint4*)a)[0] = al[0];
            ((uint4*)a)[1] = al[1];
        }
        __half* b = &Bs[buf][sRow * PITCH + sHalf * 16];
        __half2 hb[8];
#pragma unroll
        for (int j = 0; j < 8; j++) hb[j] = __floats2half2_rn(bf[2 * j], bf[2 * j + 1]);
        uint4* qb = reinterpret_cast<uint4*>(hb);
        ((uint4*)b)[0] = qb[0];
        ((uint4*)b)[1] = qb[1];
    };

    float c[4][4][4];
#pragma unroll
    for (int mi = 0; mi < 4; mi++)
#pragma unroll
        for (int ni = 0; ni < 4; ni++)
#pragma unroll
            for (int j = 0; j < 4; j++) c[mi][ni][j] = 0.f;

    fetch(0); stage(0);
    __syncthreads();

    const int KT = KTOT / 32;   // G1: 24, G2: 64
    for (int kt = 0; kt < KT; ++kt) {
        const int buf = kt & 1;
        if (kt + 1 < KT) fetch(kt + 1);
#pragma unroll
        for (int ks = 0; ks < 32; ks += 16) {
            uint32_t aF[4][4], bF[4][2];
#pragma unroll
            for (int mi = 0; mi < 4; mi++) {
                const __half* ab = &As[buf][(wm + mi * 16 + grp) * PITCH + ks + 2 * tig];
                aF[mi][0] = *(const uint32_t*)ab;
                aF[mi][1] = *(const uint32_t*)(ab + 8 * PITCH);
                aF[mi][2] = *(const uint32_t*)(ab + 8);
                aF[mi][3] = *(const uint32_t*)(ab + 8 * PITCH + 8);
            }
#pragma unroll
            for (int ni = 0; ni < 4; ni++) {
                const __half* bb = &Bs[buf][(wn + ni * 8 + grp) * PITCH + ks + 2 * tig];
                bF[ni][0] = *(const uint32_t*)bb;
                bF[ni][1] = *(const uint32_t*)(bb + 8);
            }
#pragma unroll
            for (int mi = 0; mi < 4; mi++)
#pragma unroll
                for (int ni = 0; ni < 4; ni++)
                    mma_f16(c[mi][ni][0], c[mi][ni][1], c[mi][ni][2], c[mi][ni][3],
                            aF[mi][0], aF[mi][1], aF[mi][2], aF[mi][3],
                            bF[ni][0], bF[ni][1]);
        }
        if (kt + 1 < KT) stage(buf ^ 1);
        __syncthreads();
    }

    // ---- epilogue ----
#pragma unroll
    for (int mi = 0; mi < 4; mi++) {
        const int r0 = mBase + wm + mi * 16 + grp;
        const int r1 = r0 + 8;
        const int t0 = (r0 < cnt) ? list[r0] : -1;
        const int t1 = (r1 < cnt) ? list[r1] : -1;
        float p0 = 0.f, p1 = 0.f;
        if (!G1) {
            p0 = (t0 >= 0) ? g_prob[t0] : 0.f;
            p1 = (t1 >= 0) ? g_prob[t1] : 0.f;
        }
#pragma unroll
        for (int ni = 0; ni < 4; ni++) {
            const int col = nBase + wn + ni * 8 + tig * 2;
            if (G1) {
                if (t0 >= 0) {
                    __half2 v = __floats2half2_rn(fmaxf(c[mi][ni][0], 0.f), fmaxf(c[mi][ni][1], 0.f));
                    *(__half2*)(g_latent + (size_t)t0 * HDIM + col) = v;
                }
                if (t1 >= 0) {
                    __half2 v = __floats2half2_rn(fmaxf(c[mi][ni][2], 0.f), fmaxf(c[mi][ni][3], 0.f));
                    *(__half2*)(g_latent + (size_t)t1 * HDIM + col) = v;
                }
            } else {
                const float pb0 = __ldg(pre_b + col), pb1 = __ldg(pre_b + col + 1);
                if (t0 >= 0) {
                    float2 v = make_float2(p0 * c[mi][ni][0] + pb0, p0 * c[mi][ni][1] + pb1);
                    *(float2*)(out + (size_t)t0 * DIN + col) = v;
                }
                if (t1 >= 0) {
                    float2 v = make_float2(p1 * c[mi][ni][2] + pb0, p1 * c[mi][ni][3] + pb1);
                    *(float2*)(out + (size_t)t1 * DIN + col) = v;
                }
            }
        }
    }
}

// ---------------- launcher ----------------
extern "C" void kernel_launch(void* const* d_in, const int* in_sizes, int n_in,
                              void* d_out, int out_size) {
    const float* x        = (const float*)d_in[0];
    const float* pre_b    = (const float*)d_in[1];
    const float* enc      = (const float*)d_in[2];
    const float* dec      = (const float*)d_in[3];
    const float* router_b = (const float*)d_in[4];
    const float* router   = (const float*)d_in[5];
    float* out = (float*)d_out;

    zero_counts_kernel<<<1, 32>>>();
    router_kernel<<<N_TOK / 8, 256>>>(x, router_b, router);
    build_lists_kernel<<<N_TOK / 256, 256>>>();

    dim3 g1(HDIM / 128, N_TOK / 128, NEXP);   // (16, 128, 8) — most tiles early-exit
    sae_gemm_kernel<DIN, true><<<g1, 256>>>(x, enc, pre_b, out);

    dim3 g2(DIN / 128, N_TOK / 128, NEXP);    // (6, 128, 8)
    sae_gemm_kernel<HDIM, false><<<g2, 256>>>(x, dec, pre_b, out);
}